// round 7
// baseline (speedup 1.0000x reference)
#include <cuda_runtime.h>
#include <cuda_bf16.h>

// out[b, d] = x[b, d] * clamp(diagonal[d], -0.95, 0.95)
// BATCH = 16384, LATENT_DIM = 8192, fp32. 1 GiB streamed, HBM-bound.
//
// R7: MLP=8. One CTA = one full row: TPB=256, 8 front-batched LDG.128
//     (evict-first) then 8 batched STG.128 (streaming). Doubles the
//     per-warp same-direction burst length vs R2/R6 to probe whether
//     DRAM R/W turnaround is sensitive to it. regs ~50 -> ~62% occ
//     (proven plateau-safe by R5).

#define LATENT_DIM 8192
#define BATCH 16384
#define COLS4 (LATENT_DIM / 4)        // 2048 float4 per row
#define TPB 256
#define UNROLL 8                      // TPB * UNROLL == COLS4 (one row per CTA)

__global__ __launch_bounds__(TPB)
void diag_linear_kernel(const float4* __restrict__ x,
                        const float4* __restrict__ diag,
                        float4* __restrict__ out) {
    const int col = threadIdx.x;                         // 0 .. 255
    const long long off = (long long)blockIdx.x * COLS4 + col;

    // 8 independent front-batched reads: long uninterrupted read run.
    float4 v[UNROLL];
#pragma unroll
    for (int k = 0; k < UNROLL; k++)
        v[k] = __ldcs(&x[off + k * TPB]);

    // Apply clamped diagonal (L1/L2-hot, 32 KiB) with one reused temp.
#pragma unroll
    for (int k = 0; k < UNROLL; k++) {
        float4 s = __ldg(&diag[col + k * TPB]);
        s.x = fminf(fmaxf(s.x, -0.95f), 0.95f);
        s.y = fminf(fmaxf(s.y, -0.95f), 0.95f);
        s.z = fminf(fmaxf(s.z, -0.95f), 0.95f);
        s.w = fminf(fmaxf(s.w, -0.95f), 0.95f);
        v[k].x *= s.x;
        v[k].y *= s.y;
        v[k].z *= s.z;
        v[k].w *= s.w;
    }

    // 8 batched streaming writes: long uninterrupted write run.
#pragma unroll
    for (int k = 0; k < UNROLL; k++)
        __stcs(&out[off + k * TPB], v[k]);
}

extern "C" void kernel_launch(void* const* d_in, const int* in_sizes, int n_in,
                              void* d_out, int out_size) {
    const float4* x    = (const float4*)d_in[0];
    const float4* diag = (const float4*)d_in[1];
    float4* out        = (float4*)d_out;

    diag_linear_kernel<<<BATCH, TPB>>>(x, diag, out);
}